// round 9
// baseline (speedup 1.0000x reference)
#include <cuda_runtime.h>
#include <cstdint>

#define N_BOX   2048
#define R_OUT   100
#define NT      1024
#define TOPK    256
#define SEL_T   0.905f

typedef unsigned long long u64;
typedef unsigned int u32;

// ---- shared memory layout ----
// fast path:
//   sk    u64[256]  @32768    skB u64[256] @34816
//   fsl/fst/fsr/fsb/fsha f32[256] @36864/37888/38912/39936/40960
//   fkL/fkT/fkR/fkB f32[160] @41984/42624/43264/43904
//   smaskF u32[32] @44544  spriorF u32[32] @44672
//   kidxF  int[100] @44800
//   scnt int[64] @45200   woff int[64] @45456
// fallback (clobbers everything): R3 layout
//   bufA u64[2048]@0  bufB u64[2048]@16384
//   sl2/st2/sr2/sb2/sha2 f32[2048] @0/8192/16384/24576/32768
//   kL2/kT2/kR2/kB2 f32[160] @40960/41600/42240/42880
//   smask2 @43520  sprior2 @43648  kidx2 @43776
#define SMEM_BYTES 45712

__device__ __forceinline__ void cmpex(u64& v, u64 u, bool lower, bool desc) {
    bool takeMax = (lower == desc);
    if (takeMax ? (u > v) : (u < v)) v = u;
}

__global__ __launch_bounds__(NT, 1)
void nms_kernel(const float* __restrict__ pred, float* __restrict__ out) {
    const int b    = blockIdx.x;
    const int tid  = threadIdx.x;
    const int lane = tid & 31;
    const int w    = tid >> 5;
    const u32 FULL = 0xFFFFFFFFu;
    const float* p = pred + (size_t)b * N_BOX * 5;

    extern __shared__ unsigned char smem[];
    u64*  sk   = (u64*)(smem + 32768);
    u64*  skB  = (u64*)(smem + 34816);
    float* fsl = (float*)(smem + 36864);
    float* fst = (float*)(smem + 37888);
    float* fsr = (float*)(smem + 38912);
    float* fsb = (float*)(smem + 39936);
    float* fsha= (float*)(smem + 40960);
    float* fkL = (float*)(smem + 41984);
    float* fkT = (float*)(smem + 42624);
    float* fkR = (float*)(smem + 43264);
    float* fkB = (float*)(smem + 43904);
    u32*  smaskF  = (u32*)(smem + 44544);
    u32*  spriorF = (u32*)(smem + 44672);
    int*  kidxF   = (int*)(smem + 44800);
    int*  scnt    = (int*)(smem + 45200);
    int*  woff    = (int*)(smem + 45456);
    __shared__ int s_fb, s_M, s_kept, s_nkept, s_stop;

    if (tid == 0) { s_fb = 0; s_kept = 0; s_nkept = 0; s_stop = 0; }

    // ---- Phase 1: load 2 scores/thread, build keys in regs, ballot vs SEL_T.
    // Key = (score_bits << 32) | ~idx  (score desc, idx asc tiebreak;
    // scores in [0,1) -> raw float bits order-preserving). No histogram, no atomics:
    // fixed threshold SEL_T picks M ~ 195 candidates; guards below make it exact.
    const int e0g = tid, e1g = tid + NT;
    float s0 = p[e0g * 5], s1 = p[e1g * 5];
    u64 k0 = (((u64)__float_as_uint(s0)) << 32) | (u64)(0xFFFFFFFFu - (u32)e0g);
    u64 k1 = (((u64)__float_as_uint(s1)) << 32) | (u64)(0xFFFFFFFFu - (u32)e1g);
    bool q0 = (s0 >= SEL_T), q1 = (s1 >= SEL_T);
    u32 bal0 = __ballot_sync(FULL, q0);
    u32 bal1 = __ballot_sync(FULL, q1);
    if (lane == 0) { scnt[w] = __popc(bal0); scnt[32 + w] = __popc(bal1); }
    __syncthreads();

    // ---- Phase 2: warp 0 scans the 64 warp-counts (no atomics)
    if (w == 0) {
        int a = scnt[lane], bcnt = scnt[32 + lane];
        int ia = a;
        #pragma unroll
        for (int d = 1; d < 32; d <<= 1) { int y = __shfl_up_sync(FULL, ia, d); if (lane >= d) ia += y; }
        int totA = __shfl_sync(FULL, ia, 31);
        int ib = bcnt;
        #pragma unroll
        for (int d = 1; d < 32; d <<= 1) { int y = __shfl_up_sync(FULL, ib, d); if (lane >= d) ib += y; }
        woff[lane]      = ia - a;            // exclusive, rep 0
        woff[32 + lane] = totA + ib - bcnt;  // exclusive, rep 1
        if (lane == 31) s_M = totA + ib;
    }
    __syncthreads();
    const int M = s_M;
    if (tid == 0 && M > TOPK) s_fb = 1;

    // ---- Phase 3: compaction at scanned offsets (order fixed by sort anyway)
    if (tid >= M && tid < TOPK) sk[tid] = 0;   // pads sort to tail
    {
        u32 lt = (1u << lane) - 1;
        if (q0) { int pos = woff[w]      + __popc(bal0 & lt); if (pos < TOPK) sk[pos] = k0; }
        if (q1) { int pos = woff[32 + w] + __popc(bal1 & lt); if (pos < TOPK) sk[pos] = k1; }
    }
    __syncthreads();

    if (!s_fb) {
        // ---- Phase 4: bitonic sort of 256 keys, warps 0-3 (128 thr, 2 elt/thr)
        // smem stages (j>=64): k=128 -> 1, k=256 -> 2. One named barrier each
        // (ping-pong: a buffer's re-write is separated from its reads by the
        //  next stage's barrier).
        if (w < 4) {
            const int e0 = w * 64 + lane;
            const int e1 = e0 + 32;
            u64 v0 = sk[e0], v1 = sk[e1];
            int bufsel = 0;
            for (int k = 2; k <= TOPK; k <<= 1) {
                for (int j = k >> 1; j >= 64; j >>= 1) {
                    u64* buf = bufsel ? skB : sk;
                    buf[e0] = v0; buf[e1] = v1;
                    asm volatile("bar.sync 1, 128;" ::: "memory");
                    u64 u0 = buf[e0 ^ j];
                    u64 u1 = buf[e1 ^ j];
                    cmpex(v0, u0, (e0 & j) == 0, (e0 & k) == 0);
                    cmpex(v1, u1, (e1 & j) == 0, (e1 & k) == 0);
                    bufsel ^= 1;
                }
                if (k >= 64) {
                    bool desc = ((e0 & k) == 0);
                    if (desc ? (v0 < v1) : (v0 > v1)) { u64 t = v0; v0 = v1; v1 = t; }
                }
                for (int j = ((k >> 1) < 16 ? (k >> 1) : 16); j >= 1; j >>= 1) {
                    u64 u0 = __shfl_xor_sync(FULL, v0, j);
                    u64 u1 = __shfl_xor_sync(FULL, v1, j);
                    bool lower = (lane & j) == 0;
                    cmpex(v0, u0, lower, (e0 & k) == 0);
                    cmpex(v1, u1, lower, (e1 & k) == 0);
                }
            }
            asm volatile("bar.sync 1, 128;" ::: "memory");  // last stage reads done
            sk[e0] = v0; sk[e1] = v1;
        }
        __syncthreads();

        // ---- Phase 5: gather top-M boxes into SoA (pads -> zeros)
        if (tid < TOPK) {
            if (tid < M) {
                u32 idx = 0xFFFFFFFFu - (u32)(sk[tid] & 0xFFFFFFFFu);
                const float* q = p + (size_t)idx * 5;
                float l = q[1], t = q[2], r = q[3], bo = q[4];
                fsl[tid] = l; fst[tid] = t; fsr[tid] = r; fsb[tid] = bo;
                fsha[tid] = 0.5f * ((r - l) * (bo - t));
            } else {
                fsl[tid] = 0.0f; fst[tid] = 0.0f; fsr[tid] = 0.0f; fsb[tid] = 0.0f;
                fsha[tid] = 0.0f;
            }
        }
        __syncthreads();

        // ---- Phase 6: on-demand chunked greedy over sorted prefix (exact)
        for (int base = 0; base < TOPK; base += 32) {
            {   // A: warp w = column base+w; lane = row; + kept-list test
                int nk = s_nkept;
                int bc = base + w;
                float lb = fsl[bc], tb = fst[bc], rb = fsr[bc], bb = fsb[bc], hb = fsha[bc];
                bool spv = false;
                for (int kk = lane; kk < nk; kk += 32) {
                    float iw = fminf(rb, fkR[kk]) - fmaxf(lb, fkL[kk]);
                    float ih = fminf(bb, fkB[kk]) - fmaxf(tb, fkT[kk]);
                    spv |= (fmaxf(iw, 0.0f) * fmaxf(ih, 0.0f) >= hb);
                }
                int ar = base + lane;
                float iw = fminf(rb, fsr[ar]) - fmaxf(lb, fsl[ar]);
                float ih = fminf(bb, fsb[ar]) - fmaxf(tb, fst[ar]);
                u32 m   = __ballot_sync(FULL, fmaxf(iw, 0.0f) * fmaxf(ih, 0.0f) >= hb);
                u32 spm = __ballot_sync(FULL, spv);
                if (lane == 0) { smaskF[w] = m; spriorF[w] = spm; }
            }
            __syncthreads();
            if (w == 0) {   // B: greedy resolve, rank guard < M
                int nb  = s_nkept;
                int cnt = s_kept;
                u32 kb = 0;
                #pragma unroll
                for (int a = 0; a < 32; ++a) {
                    if (base + a < M && spriorF[a] == 0 && (smaskF[a] & kb) == 0) {
                        kb |= (1u << a);
                        if (cnt < R_OUT && lane == 0) kidxF[cnt] = base + a;
                        cnt++;
                    }
                }
                bool stop = (cnt >= R_OUT);
                __syncwarp();
                if (!stop && ((kb >> lane) & 1)) {
                    int slot = nb + __popc(kb & ((1u << lane) - 1));
                    int i = base + lane;
                    fkL[slot] = fsl[i]; fkT[slot] = fst[i];
                    fkR[slot] = fsr[i]; fkB[slot] = fsb[i];
                }
                if (lane == 0) {
                    s_kept  = cnt;
                    s_nkept = nb + __popc(kb);
                    s_stop  = stop;
                }
            }
            __syncthreads();
            if (s_stop) break;
        }
        if (tid == 0 && s_kept < R_OUT) s_fb = 1;   // prefix exhausted -> exact fallback
        __syncthreads();
    }

    // =================== FALLBACK: full exact path (rebuilds keys) ===============
    if (s_fb) {
        u64*  bufA = (u64*)(smem);
        u64*  bufB = (u64*)(smem + 16384);
        float* sl2  = (float*)(smem);
        float* st2  = (float*)(smem + 8192);
        float* sr2  = (float*)(smem + 16384);
        float* sb2  = (float*)(smem + 24576);
        float* sha2 = (float*)(smem + 32768);
        float* kL2  = (float*)(smem + 40960);
        float* kT2  = (float*)(smem + 41600);
        float* kR2  = (float*)(smem + 42240);
        float* kB2  = (float*)(smem + 42880);
        u32*  smask2  = (u32*)(smem + 43520);
        u32*  sprior2 = (u32*)(smem + 43648);
        int*  kidx2   = (int*)(smem + 43776);

        const int e0 = w * 64 + lane;
        const int e1 = e0 + 32;
        u64 v0 = (((u64)__float_as_uint(p[e0 * 5])) << 32) | (u64)(0xFFFFFFFFu - (u32)e0);
        u64 v1 = (((u64)__float_as_uint(p[e1 * 5])) << 32) | (u64)(0xFFFFFFFFu - (u32)e1);
        __syncthreads();

        int bufsel = 0;
        for (int k = 2; k <= N_BOX; k <<= 1) {
            for (int j = k >> 1; j >= 64; j >>= 1) {
                u64* buf = bufsel ? bufB : bufA;
                buf[e0] = v0; buf[e1] = v1;
                __syncthreads();
                u64 u0 = buf[e0 ^ j];
                u64 u1 = buf[e1 ^ j];
                cmpex(v0, u0, (e0 & j) == 0, (e0 & k) == 0);
                cmpex(v1, u1, (e1 & j) == 0, (e1 & k) == 0);
                bufsel ^= 1;
                __syncthreads();
            }
            if (k >= 64) {
                bool desc = ((e0 & k) == 0);
                if (desc ? (v0 < v1) : (v0 > v1)) { u64 t = v0; v0 = v1; v1 = t; }
            }
            for (int j = ((k >> 1) < 16 ? (k >> 1) : 16); j >= 1; j >>= 1) {
                u64 u0 = __shfl_xor_sync(FULL, v0, j);
                u64 u1 = __shfl_xor_sync(FULL, v1, j);
                bool lower = (lane & j) == 0;
                cmpex(v0, u0, lower, (e0 & k) == 0);
                cmpex(v1, u1, lower, (e1 & k) == 0);
            }
        }
        __syncthreads();

        {
            u32 i0 = 0xFFFFFFFFu - (u32)(v0 & 0xFFFFFFFFu);
            u32 i1 = 0xFFFFFFFFu - (u32)(v1 & 0xFFFFFFFFu);
            const float* q = p + (size_t)i0 * 5;
            float l = q[1], t = q[2], r = q[3], bo = q[4];
            sl2[e0] = l; st2[e0] = t; sr2[e0] = r; sb2[e0] = bo;
            sha2[e0] = 0.5f * ((r - l) * (bo - t));
            q = p + (size_t)i1 * 5;
            l = q[1]; t = q[2]; r = q[3]; bo = q[4];
            sl2[e1] = l; st2[e1] = t; sr2[e1] = r; sb2[e1] = bo;
            sha2[e1] = 0.5f * ((r - l) * (bo - t));
        }
        if (tid == 0) { s_kept = 0; s_nkept = 0; s_stop = 0; }
        __syncthreads();

        for (int base = 0; base < N_BOX; base += 32) {
            {
                int nk = s_nkept;
                int bc = base + w;
                float lb = sl2[bc], tb = st2[bc], rb = sr2[bc], bb = sb2[bc], hb = sha2[bc];
                bool spv = false;
                for (int kk = lane; kk < nk; kk += 32) {
                    float iw = fminf(rb, kR2[kk]) - fmaxf(lb, kL2[kk]);
                    float ih = fminf(bb, kB2[kk]) - fmaxf(tb, kT2[kk]);
                    spv |= (fmaxf(iw, 0.0f) * fmaxf(ih, 0.0f) >= hb);
                }
                int ar = base + lane;
                float iw = fminf(rb, sr2[ar]) - fmaxf(lb, sl2[ar]);
                float ih = fminf(bb, sb2[ar]) - fmaxf(tb, st2[ar]);
                u32 m   = __ballot_sync(FULL, fmaxf(iw, 0.0f) * fmaxf(ih, 0.0f) >= hb);
                u32 spm = __ballot_sync(FULL, spv);
                if (lane == 0) { smask2[w] = m; sprior2[w] = spm; }
            }
            __syncthreads();
            if (w == 0) {
                int nb  = s_nkept;
                int cnt = s_kept;
                u32 kb = 0;
                #pragma unroll
                for (int a = 0; a < 32; ++a) {
                    if (sprior2[a] == 0 && (smask2[a] & kb) == 0) {
                        kb |= (1u << a);
                        if (cnt < R_OUT && lane == 0) kidx2[cnt] = base + a;
                        cnt++;
                    }
                }
                bool stop = (cnt >= R_OUT);
                __syncwarp();
                if (!stop && ((kb >> lane) & 1)) {
                    int slot = nb + __popc(kb & ((1u << lane) - 1));
                    int i = base + lane;
                    kL2[slot] = sl2[i]; kT2[slot] = st2[i];
                    kR2[slot] = sr2[i]; kB2[slot] = sb2[i];
                }
                if (lane == 0) {
                    s_kept  = cnt;
                    s_nkept = nb + __popc(kb);
                    s_stop  = stop;
                }
            }
            __syncthreads();
            if (s_stop) break;
        }
        __syncthreads();

        int nk = s_kept; if (nk > R_OUT) nk = R_OUT;
        float* ob = out + (size_t)b * R_OUT * 3;
        if (tid < R_OUT) {
            int s = tid;
            if (s < nk) {
                int i = kidx2[s];
                ob[s * 3 + 0] = st2[i];
                ob[s * 3 + 1] = sr2[i];
                ob[s * 3 + 2] = sb2[i];
            } else {
                ob[s * 3 + 0] = 0.0f;
                ob[s * 3 + 1] = 0.0f;
                ob[s * 3 + 2] = 0.0f;
            }
        }
        return;
    }

    // ---- fast-path output: (top, right, bottom) for first R kept, zeros after
    int nk = s_kept; if (nk > R_OUT) nk = R_OUT;
    float* ob = out + (size_t)b * R_OUT * 3;
    if (tid < R_OUT) {
        int s = tid;
        if (s < nk) {
            int i = kidxF[s];
            ob[s * 3 + 0] = fst[i];
            ob[s * 3 + 1] = fsr[i];
            ob[s * 3 + 2] = fsb[i];
        } else {
            ob[s * 3 + 0] = 0.0f;
            ob[s * 3 + 1] = 0.0f;
            ob[s * 3 + 2] = 0.0f;
        }
    }
}

extern "C" void kernel_launch(void* const* d_in, const int* in_sizes, int n_in,
                              void* d_out, int out_size) {
    const float* pred = (const float*)d_in[0];
    float* out = (float*)d_out;
    (void)in_sizes; (void)n_in; (void)out_size;
    nms_kernel<<<32, NT, SMEM_BYTES>>>(pred, out);
}

// round 10
// speedup vs baseline: 1.0998x; 1.0998x over previous
#include <cuda_runtime.h>
#include <cstdint>

#define N_BOX   2048
#define R_OUT   100
#define NT      1024
#define TOPK    256
#define SEL_T   0.905f

typedef unsigned long long u64;
typedef unsigned int u32;

// ---- shared memory layout ----
// fast path:
//   sk     u32[256]    @32768
//   skB    u32[256]    @33792
//   candIdx int[256]   @34816
//   bltrb  float4[256] @36864   (slot order, permuted in place to rank order)
//   bsha   f32[256]    @40960   (0.5*area)
//   fkLTRB float4[160] @41984   (compact kept list)
//   smaskF u32[32] @44544  spriorF u32[32] @44672
//   kidxF  int[100] @44800
//   scnt int[64] @45200   woff int[64] @45456
// fallback (clobbers everything): R3 layout
//   bufA u64[2048]@0  bufB u64[2048]@16384
//   sl2/st2/sr2/sb2/sha2 f32[2048] @0/8192/16384/24576/32768
//   kL2/kT2/kR2/kB2 f32[160] @40960/41600/42240/42880
//   smask2 @43520  sprior2 @43648  kidx2 @43776
#define SMEM_BYTES 45712

__device__ __forceinline__ void cmpex64(u64& v, u64 u, bool lower, bool desc) {
    bool takeMax = (lower == desc);
    if (takeMax ? (u > v) : (u < v)) v = u;
}
__device__ __forceinline__ void cmpex32(u32& v, u32 u, bool lower, bool desc) {
    bool takeMax = (lower == desc);
    if (takeMax ? (u > v) : (u < v)) v = u;
}

__global__ __launch_bounds__(NT, 1)
void nms_kernel(const float* __restrict__ pred, float* __restrict__ out) {
    const int b    = blockIdx.x;
    const int tid  = threadIdx.x;
    const int lane = tid & 31;
    const int w    = tid >> 5;
    const u32 FULL = 0xFFFFFFFFu;
    const float* p = pred + (size_t)b * N_BOX * 5;

    extern __shared__ unsigned char smem[];
    u32*    sk      = (u32*)(smem + 32768);
    u32*    skB     = (u32*)(smem + 33792);
    int*    candIdx = (int*)(smem + 34816);
    float4* bltrb   = (float4*)(smem + 36864);
    float*  bsha    = (float*)(smem + 40960);
    float4* fkLTRB  = (float4*)(smem + 41984);
    u32*    smaskF  = (u32*)(smem + 44544);
    u32*    spriorF = (u32*)(smem + 44672);
    int*    kidxF   = (int*)(smem + 44800);
    int*    scnt    = (int*)(smem + 45200);
    int*    woff    = (int*)(smem + 45456);
    __shared__ int s_fb, s_M, s_kept, s_nkept, s_stop;

    if (tid == 0) { s_fb = 0; s_kept = 0; s_nkept = 0; s_stop = 0; }

    // ---- Phase 1: 2 scores/thread, ballot vs SEL_T.
    // All selected scores lie in [SEL_T, 1.0): same sign/exponent (126), so
    // mantissa order == value order -> u32 sort keys below. Guard s >= 1.0 -> fallback.
    const int e0g = tid, e1g = tid + NT;
    float s0 = p[e0g * 5], s1 = p[e1g * 5];
    u32 sb0 = __float_as_uint(s0), sb1 = __float_as_uint(s1);
    bool q0 = (s0 >= SEL_T), q1 = (s1 >= SEL_T);
    if ((s0 >= 1.0f) || (s1 >= 1.0f)) s_fb = 1;   // benign race, all write 1
    u32 bal0 = __ballot_sync(FULL, q0);
    u32 bal1 = __ballot_sync(FULL, q1);
    if (lane == 0) { scnt[w] = __popc(bal0); scnt[32 + w] = __popc(bal1); }
    __syncthreads();

    // ---- Phase 2: warp 0 scans the 64 warp-counts
    if (w == 0) {
        int a = scnt[lane], bcnt = scnt[32 + lane];
        int ia = a;
        #pragma unroll
        for (int d = 1; d < 32; d <<= 1) { int y = __shfl_up_sync(FULL, ia, d); if (lane >= d) ia += y; }
        int totA = __shfl_sync(FULL, ia, 31);
        int ib = bcnt;
        #pragma unroll
        for (int d = 1; d < 32; d <<= 1) { int y = __shfl_up_sync(FULL, ib, d); if (lane >= d) ib += y; }
        woff[lane]      = ia - a;
        woff[32 + lane] = totA + ib - bcnt;
        if (lane == 31) s_M = totA + ib;
    }
    __syncthreads();
    const int M = s_M;
    if (tid == 0 && M > TOPK) s_fb = 1;

    // ---- Phase 3: compaction. Key = (score_bits<<9) | (511 - slot).
    // Compaction preserves original index order, so slot asc == idx asc (stable).
    if (tid >= M && tid < TOPK) sk[tid] = 0;   // pads (real keys have low9 >= 256 > 0)
    {
        u32 lt = (1u << lane) - 1;
        if (q0) {
            int pos = woff[w] + __popc(bal0 & lt);
            if (pos < TOPK) { sk[pos] = (sb0 << 9) | (u32)(511 - pos); candIdx[pos] = e0g; }
        }
        if (q1) {
            int pos = woff[32 + w] + __popc(bal1 & lt);
            if (pos < TOPK) { sk[pos] = (sb1 << 9) | (u32)(511 - pos); candIdx[pos] = e1g; }
        }
    }
    __syncthreads();

    if (!s_fb) {
        // ---- Phase 4 (split): warps 0-3 sort keys; warps 4-11 gather boxes
        // (slot order) from GMEM concurrently. Named barrier 1 = sorter-only.
        if (w < 4) {
            const int e0 = w * 64 + lane;
            const int e1 = e0 + 32;
            u32 v0 = sk[e0], v1 = sk[e1];
            int bufsel = 0;
            for (int k = 2; k <= TOPK; k <<= 1) {
                for (int j = k >> 1; j >= 64; j >>= 1) {
                    u32* buf = bufsel ? skB : sk;
                    buf[e0] = v0; buf[e1] = v1;
                    asm volatile("bar.sync 1, 128;" ::: "memory");
                    u32 u0 = buf[e0 ^ j];
                    u32 u1 = buf[e1 ^ j];
                    cmpex32(v0, u0, (e0 & j) == 0, (e0 & k) == 0);
                    cmpex32(v1, u1, (e1 & j) == 0, (e1 & k) == 0);
                    bufsel ^= 1;
                }
                if (k >= 64) {
                    bool desc = ((e0 & k) == 0);
                    if (desc ? (v0 < v1) : (v0 > v1)) { u32 t = v0; v0 = v1; v1 = t; }
                }
                for (int j = ((k >> 1) < 16 ? (k >> 1) : 16); j >= 1; j >>= 1) {
                    u32 u0 = __shfl_xor_sync(FULL, v0, j);
                    u32 u1 = __shfl_xor_sync(FULL, v1, j);
                    bool lower = (lane & j) == 0;
                    cmpex32(v0, u0, lower, (e0 & k) == 0);
                    cmpex32(v1, u1, lower, (e1 & k) == 0);
                }
            }
            asm volatile("bar.sync 1, 128;" ::: "memory");  // last stage reads done
            sk[e0] = v0; sk[e1] = v1;
        } else {
            int c = tid - 128;                 // warps 4-11 cover c = 0..255
            if (c < TOPK) {
                if (c < M) {
                    int idx = candIdx[c];
                    const float* q = p + (size_t)idx * 5;
                    float l = q[1], t = q[2], r = q[3], bo = q[4];
                    bltrb[c] = make_float4(l, t, r, bo);
                    bsha[c]  = 0.5f * ((r - l) * (bo - t));
                } else {
                    bltrb[c] = make_float4(0.f, 0.f, 0.f, 0.f);
                    bsha[c]  = 0.f;
                }
            }
        }
        __syncthreads();

        // ---- Phase 5: in-place permute slot-order -> rank-order (smem only)
        float4 f4 = make_float4(0.f, 0.f, 0.f, 0.f);
        float  sh = 0.f;
        if (tid < TOPK && tid < M) {
            int slot = 511 - (int)(sk[tid] & 0x1FFu);
            f4 = bltrb[slot];
            sh = bsha[slot];
        }
        __syncthreads();
        if (tid < TOPK) { bltrb[tid] = f4; bsha[tid] = sh; }
        __syncthreads();

        // ---- Phase 6: on-demand chunked greedy over sorted prefix (exact)
        for (int base = 0; base < TOPK; base += 32) {
            {   // A: warp w = column base+w; lane = row; + kept-list test
                int nk = s_nkept;
                int bc = base + w;
                float4 c4 = bltrb[bc];
                float  hb = bsha[bc];
                bool spv = false;
                for (int kk = lane; kk < nk; kk += 32) {
                    float4 k4 = fkLTRB[kk];
                    float iw = fminf(c4.z, k4.z) - fmaxf(c4.x, k4.x);
                    float ih = fminf(c4.w, k4.w) - fmaxf(c4.y, k4.y);
                    spv |= (fmaxf(iw, 0.0f) * fmaxf(ih, 0.0f) >= hb);
                }
                float4 r4 = bltrb[base + lane];
                float iw = fminf(c4.z, r4.z) - fmaxf(c4.x, r4.x);
                float ih = fminf(c4.w, r4.w) - fmaxf(c4.y, r4.y);
                u32 m   = __ballot_sync(FULL, fmaxf(iw, 0.0f) * fmaxf(ih, 0.0f) >= hb);
                u32 spm = __ballot_sync(FULL, spv);
                if (lane == 0) { smaskF[w] = m; spriorF[w] = spm; }
            }
            __syncthreads();
            if (w == 0) {   // B: greedy resolve, rank guard < M
                int nb  = s_nkept;
                int cnt = s_kept;
                u32 kb = 0;
                #pragma unroll
                for (int a = 0; a < 32; ++a) {
                    if (base + a < M && spriorF[a] == 0 && (smaskF[a] & kb) == 0) {
                        kb |= (1u << a);
                        if (cnt < R_OUT && lane == 0) kidxF[cnt] = base + a;
                        cnt++;
                    }
                }
                bool stop = (cnt >= R_OUT);
                __syncwarp();
                if (!stop && ((kb >> lane) & 1)) {
                    int slot = nb + __popc(kb & ((1u << lane) - 1));
                    fkLTRB[slot] = bltrb[base + lane];
                }
                if (lane == 0) {
                    s_kept  = cnt;
                    s_nkept = nb + __popc(kb);
                    s_stop  = stop;
                }
            }
            __syncthreads();
            if (s_stop) break;
        }
        if (tid == 0 && s_kept < R_OUT) s_fb = 1;   // prefix exhausted -> exact fallback
        __syncthreads();
    }

    // =================== FALLBACK: full exact path (rebuilds keys) ===============
    if (s_fb) {
        u64*  bufA = (u64*)(smem);
        u64*  bufB = (u64*)(smem + 16384);
        float* sl2  = (float*)(smem);
        float* st2  = (float*)(smem + 8192);
        float* sr2  = (float*)(smem + 16384);
        float* sb2  = (float*)(smem + 24576);
        float* sha2 = (float*)(smem + 32768);
        float* kL2  = (float*)(smem + 40960);
        float* kT2  = (float*)(smem + 41600);
        float* kR2  = (float*)(smem + 42240);
        float* kB2  = (float*)(smem + 42880);
        u32*  smask2  = (u32*)(smem + 43520);
        u32*  sprior2 = (u32*)(smem + 43648);
        int*  kidx2   = (int*)(smem + 43776);

        const int e0 = w * 64 + lane;
        const int e1 = e0 + 32;
        u64 v0 = (((u64)__float_as_uint(p[e0 * 5])) << 32) | (u64)(0xFFFFFFFFu - (u32)e0);
        u64 v1 = (((u64)__float_as_uint(p[e1 * 5])) << 32) | (u64)(0xFFFFFFFFu - (u32)e1);
        __syncthreads();

        int bufsel = 0;
        for (int k = 2; k <= N_BOX; k <<= 1) {
            for (int j = k >> 1; j >= 64; j >>= 1) {
                u64* buf = bufsel ? bufB : bufA;
                buf[e0] = v0; buf[e1] = v1;
                __syncthreads();
                u64 u0 = buf[e0 ^ j];
                u64 u1 = buf[e1 ^ j];
                cmpex64(v0, u0, (e0 & j) == 0, (e0 & k) == 0);
                cmpex64(v1, u1, (e1 & j) == 0, (e1 & k) == 0);
                bufsel ^= 1;
                __syncthreads();
            }
            if (k >= 64) {
                bool desc = ((e0 & k) == 0);
                if (desc ? (v0 < v1) : (v0 > v1)) { u64 t = v0; v0 = v1; v1 = t; }
            }
            for (int j = ((k >> 1) < 16 ? (k >> 1) : 16); j >= 1; j >>= 1) {
                u64 u0 = __shfl_xor_sync(FULL, v0, j);
                u64 u1 = __shfl_xor_sync(FULL, v1, j);
                bool lower = (lane & j) == 0;
                cmpex64(v0, u0, lower, (e0 & k) == 0);
                cmpex64(v1, u1, lower, (e1 & k) == 0);
            }
        }
        __syncthreads();

        {
            u32 i0 = 0xFFFFFFFFu - (u32)(v0 & 0xFFFFFFFFu);
            u32 i1 = 0xFFFFFFFFu - (u32)(v1 & 0xFFFFFFFFu);
            const float* q = p + (size_t)i0 * 5;
            float l = q[1], t = q[2], r = q[3], bo = q[4];
            sl2[e0] = l; st2[e0] = t; sr2[e0] = r; sb2[e0] = bo;
            sha2[e0] = 0.5f * ((r - l) * (bo - t));
            q = p + (size_t)i1 * 5;
            l = q[1]; t = q[2]; r = q[3]; bo = q[4];
            sl2[e1] = l; st2[e1] = t; sr2[e1] = r; sb2[e1] = bo;
            sha2[e1] = 0.5f * ((r - l) * (bo - t));
        }
        if (tid == 0) { s_kept = 0; s_nkept = 0; s_stop = 0; }
        __syncthreads();

        for (int base = 0; base < N_BOX; base += 32) {
            {
                int nk = s_nkept;
                int bc = base + w;
                float lb = sl2[bc], tb = st2[bc], rb = sr2[bc], bb = sb2[bc], hb = sha2[bc];
                bool spv = false;
                for (int kk = lane; kk < nk; kk += 32) {
                    float iw = fminf(rb, kR2[kk]) - fmaxf(lb, kL2[kk]);
                    float ih = fminf(bb, kB2[kk]) - fmaxf(tb, kT2[kk]);
                    spv |= (fmaxf(iw, 0.0f) * fmaxf(ih, 0.0f) >= hb);
                }
                int ar = base + lane;
                float iw = fminf(rb, sr2[ar]) - fmaxf(lb, sl2[ar]);
                float ih = fminf(bb, sb2[ar]) - fmaxf(tb, st2[ar]);
                u32 m   = __ballot_sync(FULL, fmaxf(iw, 0.0f) * fmaxf(ih, 0.0f) >= hb);
                u32 spm = __ballot_sync(FULL, spv);
                if (lane == 0) { smask2[w] = m; sprior2[w] = spm; }
            }
            __syncthreads();
            if (w == 0) {
                int nb  = s_nkept;
                int cnt = s_kept;
                u32 kb = 0;
                #pragma unroll
                for (int a = 0; a < 32; ++a) {
                    if (sprior2[a] == 0 && (smask2[a] & kb) == 0) {
                        kb |= (1u << a);
                        if (cnt < R_OUT && lane == 0) kidx2[cnt] = base + a;
                        cnt++;
                    }
                }
                bool stop = (cnt >= R_OUT);
                __syncwarp();
                if (!stop && ((kb >> lane) & 1)) {
                    int slot = nb + __popc(kb & ((1u << lane) - 1));
                    int i = base + lane;
                    kL2[slot] = sl2[i]; kT2[slot] = st2[i];
                    kR2[slot] = sr2[i]; kB2[slot] = sb2[i];
                }
                if (lane == 0) {
                    s_kept  = cnt;
                    s_nkept = nb + __popc(kb);
                    s_stop  = stop;
                }
            }
            __syncthreads();
            if (s_stop) break;
        }
        __syncthreads();

        int nk = s_kept; if (nk > R_OUT) nk = R_OUT;
        float* ob = out + (size_t)b * R_OUT * 3;
        if (tid < R_OUT) {
            int s = tid;
            if (s < nk) {
                int i = kidx2[s];
                ob[s * 3 + 0] = st2[i];
                ob[s * 3 + 1] = sr2[i];
                ob[s * 3 + 2] = sb2[i];
            } else {
                ob[s * 3 + 0] = 0.0f;
                ob[s * 3 + 1] = 0.0f;
                ob[s * 3 + 2] = 0.0f;
            }
        }
        return;
    }

    // ---- fast-path output: (top, right, bottom) for first R kept, zeros after
    int nk = s_kept; if (nk > R_OUT) nk = R_OUT;
    float* ob = out + (size_t)b * R_OUT * 3;
    if (tid < R_OUT) {
        int s = tid;
        if (s < nk) {
            float4 f = bltrb[kidxF[s]];
            ob[s * 3 + 0] = f.y;   // top
            ob[s * 3 + 1] = f.z;   // right
            ob[s * 3 + 2] = f.w;   // bottom
        } else {
            ob[s * 3 + 0] = 0.0f;
            ob[s * 3 + 1] = 0.0f;
            ob[s * 3 + 2] = 0.0f;
        }
    }
}

extern "C" void kernel_launch(void* const* d_in, const int* in_sizes, int n_in,
                              void* d_out, int out_size) {
    const float* pred = (const float*)d_in[0];
    float* out = (float*)d_out;
    (void)in_sizes; (void)n_in; (void)out_size;
    nms_kernel<<<32, NT, SMEM_BYTES>>>(pred, out);
}